// round 8
// baseline (speedup 1.0000x reference)
#include <cuda_runtime.h>
#include <cstdint>

#define NIMG      32
#define IMH       512
#define IMW       512
#define PATCH     13
#define OWIDTH    500
#define OHEIGHT   500
#define SW        8          // output cols per thread
#define SH        14         // output rows per band (last band: 10)
#define NBANDS    36         // 35*14 + 10 = 500 output rows
#define THREADS   64
#define ROWF      528        // staged row pitch (512 data + 16 zero pad floats)
#define EPSF      1e-5f

// per-(image,band) partials: [ccsum, S1, S2, S11, S22, S12]
__device__ float g_part[NIMG * NBANDS * 6];
__device__ unsigned int g_cnt[NIMG];   // zero-init; reset by finalizer each launch

// ---------------- cp.async helpers ----------------
__device__ __forceinline__ void cpa16(uint32_t saddr, const float* g) {
    asm volatile("cp.async.cg.shared.global [%0], [%1], 16;" :: "r"(saddr), "l"(g));
}
__device__ __forceinline__ void cpa_commit() {
    asm volatile("cp.async.commit_group;" ::: "memory");
}
__device__ __forceinline__ void cpa_wait0() {
    asm volatile("cp.async.wait_group 0;" ::: "memory");
}

// read 20 floats (5 x LDS.128) from a staged row at column 8*t
__device__ __forceinline__ void lds20(const float* __restrict__ s, float v[20]) {
#pragma unroll
    for (int i = 0; i < 5; i++) {
        float4 q = reinterpret_cast<const float4*>(s)[i];
        v[4*i+0] = q.x; v[4*i+1] = q.y; v[4*i+2] = q.z; v[4*i+3] = q.w;
    }
}

// Add (ADD=true) or subtract the horizontal 13-tap sums of one input row into
// the per-thread 2D box accumulators for its SW output columns.
template<bool ADD>
__device__ __forceinline__ void accum_strip(float S0[SW], float S1[SW], float S2[SW],
                                            float S3[SW], float S4[SW],
                                            const float a[20], const float b[20]) {
    float h0 = 0.f, h1 = 0.f, h2 = 0.f, h3 = 0.f, h4 = 0.f;
#pragma unroll
    for (int k = 0; k < PATCH; k++) {
        float xa = a[k], xb = b[k];
        h0 += xa;
        h1 += xb;
        h2 = fmaf(xa, xa, h2);
        h3 = fmaf(xb, xb, h3);
        h4 = fmaf(xa, xb, h4);
    }
#pragma unroll
    for (int j = 0; j < SW; j++) {
        if (j > 0) {
            float xa = a[j + 12], xb = b[j + 12];
            float ya = a[j - 1],  yb = b[j - 1];
            h0 += xa - ya;
            h1 += xb - yb;
            h2 += fmaf(xa, xa, -(ya * ya));
            h3 += fmaf(xb, xb, -(yb * yb));
            h4 += fmaf(xa, xb, -(ya * yb));
        }
        if (ADD) { S0[j] += h0; S1[j] += h1; S2[j] += h2; S3[j] += h3; S4[j] += h4; }
        else     { S0[j] -= h0; S1[j] -= h1; S2[j] -= h2; S3[j] -= h3; S4[j] -= h4; }
    }
}

// Global-NCC partial sums: every thread owns EXACTLY its 8 columns
// (64 threads * 8 = 512 — complete, disjoint coverage).
__device__ __forceinline__ void accum_global(float gs[5], const float a[20],
                                             const float b[20]) {
#pragma unroll
    for (int j = 0; j < SW; j++) {
        float xa = a[j], xb = b[j];
        gs[0] += xa; gs[1] += xb;
        gs[2] = fmaf(xa, xa, gs[2]);
        gs[3] = fmaf(xb, xb, gs[3]);
        gs[4] = fmaf(xa, xb, gs[4]);
    }
}

__global__ void __launch_bounds__(THREADS, 8)
ncc_fused_kernel(const float* __restrict__ x1, const float* __restrict__ x2,
                 float* __restrict__ out) {
    // staged rows: [buf][slot][col]; slots: 0=in_x1, 1=in_x2, 2=out_x1, 3=out_x2
    __shared__ float stage[2][4][ROWF];

    const int band = blockIdx.x;
    const int img  = blockIdx.y;
    const int t    = threadIdx.x;
    const bool last_band = (band == NBANDS - 1);

    const int c0 = t * SW;
    const int r0 = band * SH;                     // last band: r0 = 490
    const int Eb = (OHEIGHT - r0) < SH ? (OHEIGHT - r0) : SH;   // emitted rows
    const int E  = PATCH + Eb - 1;                // total staged events
    int nv = OWIDTH - c0; if (nv > SW) nv = SW;   // <=0 for t=63
    const int nvalid = nv;

    const float* __restrict__ b1 = x1 + (size_t)img * IMH * IMW;
    const float* __restrict__ b2 = x2 + (size_t)img * IMH * IMW;

    // zero the pad columns (512..527) of all 8 row slots once; threads 62/63
    // read these zeros in their 20-col windows.
    {
        int s = t >> 3;          // slot group 0..7
        int o = (t & 7) * 2;     // 0,2,..,14
        stage[s >> 2][s & 3][512 + o]     = 0.f;
        stage[s >> 2][s & 3][512 + o + 1] = 0.f;
    }

    float S0[SW], S1[SW], S2[SW], S3[SW], S4[SW];
#pragma unroll
    for (int j = 0; j < SW; j++) { S0[j]=0.f; S1[j]=0.f; S2[j]=0.f; S3[j]=0.f; S4[j]=0.f; }
    float gs[5] = {0.f, 0.f, 0.f, 0.f, 0.f};
    float ccacc = 0.f;

    const float N169 = 169.0f;
    const float EPS2 = 169.0f * 169.0f * EPSF;

    // ---- stage event 0 (in-row r0): each thread stages its 32B of each row
    {
        uint32_t sb = (uint32_t)__cvta_generic_to_shared(&stage[0][0][0]) + t * 32u;
        const float* g1 = b1 + (size_t)r0 * IMW + t * 8;
        const float* g2 = b2 + (size_t)r0 * IMW + t * 8;
        cpa16(sb,                 g1);
        cpa16(sb + 16,            g1 + 4);
        cpa16(sb + ROWF * 4,      g2);
        cpa16(sb + ROWF * 4 + 16, g2 + 4);
        cpa_commit();
    }

#pragma unroll 1
    for (int e = 0; e < 26; e++) {        // max E = 26; exit checked below
        if (e >= E) break;
        cpa_wait0();
        __syncthreads();

        // stage event e+1 into the other buffer (in-row always; out-row if due)
        if (e + 1 < E) {
            const int nb  = (e + 1) & 1;
            const int rin = r0 + e + 1;
            uint32_t sb = (uint32_t)__cvta_generic_to_shared(&stage[nb][0][0]) + t * 32u;
            const float* g1 = b1 + (size_t)rin * IMW + t * 8;
            const float* g2 = b2 + (size_t)rin * IMW + t * 8;
            cpa16(sb,                 g1);
            cpa16(sb + 16,            g1 + 4);
            cpa16(sb + ROWF * 4,      g2);
            cpa16(sb + ROWF * 4 + 16, g2 + 4);
            if (e + 1 >= PATCH) {
                const int rout = r0 + e + 1 - PATCH;
                const float* o1 = b1 + (size_t)rout * IMW + t * 8;
                const float* o2 = b2 + (size_t)rout * IMW + t * 8;
                cpa16(sb + 2 * ROWF * 4,      o1);
                cpa16(sb + 2 * ROWF * 4 + 16, o1 + 4);
                cpa16(sb + 3 * ROWF * 4,      o2);
                cpa16(sb + 3 * ROWF * 4 + 16, o2 + 4);
            }
            cpa_commit();
        } else {
            cpa_commit();   // keep group count in lockstep with waits
        }

        // ---- consume event e from buf e&1
        const int cb = e & 1;
        float a[20], bb[20];
        lds20(&stage[cb][0][c0], a);
        lds20(&stage[cb][1][c0], bb);
        accum_strip<true>(S0, S1, S2, S3, S4, a, bb);
        // row r0+e owned for global sums iff within band's SH rows, or last band
        if ((e < SH) || last_band)
            accum_global(gs, a, bb);

        if (e >= PATCH) {
            lds20(&stage[cb][2][c0], a);
            lds20(&stage[cb][3][c0], bb);
            accum_strip<false>(S0, S1, S2, S3, S4, a, bb);
        }

        // ---- emit cc for output row r0 + (e - 12) once window is full
        if (e >= PATCH - 1) {
#pragma unroll
            for (int j = 0; j < SW; j++) {
                if (j < nvalid) {
                    float s1 = S0[j], s2 = S1[j];
                    float u1 = fmaf(S2[j], N169, EPS2) - s1 * s1;
                    float u2 = fmaf(S3[j], N169, EPS2) - s2 * s2;
                    float A  = fmaf(S4[j], N169, -(s1 * s2));
                    ccacc = fmaf(A, rsqrtf(u1 * u2), ccacc);
                }
            }
        }
    }

    // ---- deterministic block reduction of (ccacc, gs[0..4])
    float vals[6] = {ccacc, gs[0], gs[1], gs[2], gs[3], gs[4]};
#pragma unroll
    for (int off = 16; off > 0; off >>= 1) {
#pragma unroll
        for (int q = 0; q < 6; q++)
            vals[q] += __shfl_down_sync(0xffffffffu, vals[q], off);
    }
    __shared__ float red[THREADS / 32][6];
    __shared__ bool  is_last;
    const int w = t >> 5, l = t & 31;
    if (l == 0) {
#pragma unroll
        for (int q = 0; q < 6; q++) red[w][q] = vals[q];
    }
    __syncthreads();
    if (t == 0) {
        float* dst = g_part + ((size_t)img * NBANDS + band) * 6;
#pragma unroll
        for (int q = 0; q < 6; q++)
            dst[q] = red[0][q] + red[1][q];
        __threadfence();
        unsigned old = atomicAdd(&g_cnt[img], 1u);
        is_last = (old == NBANDS - 1);
    }
    __syncthreads();

    // ---- last arriving block for this image finalizes (fixed-order sums)
    if (is_last) {
        __threadfence();
        __shared__ float comp[6];
        if (t < 6) {
            const float* src = g_part + (size_t)img * NBANDS * 6;
            float acc = 0.f;
#pragma unroll 1
            for (int k = 0; k < NBANDS; k++)
                acc += src[k * 6 + t];
            comp[t] = acc;
        }
        __syncthreads();
        if (t == 0) {
            const float ccsum = comp[0];
            const float s1 = comp[1], s2 = comp[2];
            const float s11 = comp[3], s22 = comp[4], s12 = comp[5];
            const float invN = 1.0f / (float)(IMH * IMW);
            const float m1 = s1 * invN;
            const float m2 = s2 * invN;
            const float v1 = fmaf(s11, invN, -(m1 * m1)) + EPSF;
            const float v2 = fmaf(s22, invN, -(m2 * m2)) + EPSF;
            const float g  = fmaf(s12, invN, -(m1 * m2)) * rsqrtf(v1 * v2);
            const float p  = ccsum * (1.0f / (500.0f * 500.0f));  // n folded out
            out[img] = 0.5f * g + 0.5f * p;
            g_cnt[img] = 0;   // reset for next launch / graph replay
        }
    }
}

extern "C" void kernel_launch(void* const* d_in, const int* in_sizes, int n_in,
                              void* d_out, int out_size) {
    const float* x1 = (const float*)d_in[0];
    const float* x2 = (const float*)d_in[1];
    float* out = (float*)d_out;

    dim3 grid(NBANDS, NIMG);
    ncc_fused_kernel<<<grid, THREADS>>>(x1, x2, out);
}